// round 11
// baseline (speedup 1.0000x reference)
#include <cuda_runtime.h>
#include <cstdint>

// ----------------------------------------------------------------------------
// TitleGenerator fused kernel, round 8: occupancy attack.
// 148 CTAs x 960 threads (30 warps, was 19 -> latency-bound at issue=28%).
//  threads 0..703  : split-K. row = t>>1 (0..351), K-half = t&1 (64 k each).
//                    lane pairs (2r, 2r+1) reduce via shfl_xor(1).
//                    rows 0..319 weights SMEM-resident; 320..351 streamed.
//  threads 704..959: full-K rows 352..607, weights streamed from L2 with
//                    4-deep prefetch (8 warps, spread across SMSPs).
// Same math as R6/R7 (combined weights exploiting x==h after step 1),
// period-2 bitwise fixed-point detection.
// ----------------------------------------------------------------------------

#define BB      2048
#define HH      128
#define CC      96
#define TSTEPS  400
#define NT      960
#define NWS     320                   // weight rows resident in SMEM
#define TITLES_ELEMS 78643200         // 2048*400*96

// dynamic smem layout (bytes)
#define OFF_W    0
#define SZ_W     (32 * NWS * 16)               // 163840
#define OFF_XH   (OFF_W + SZ_W)                // 163840
#define OFF_XL   (OFF_XH + 14 * 128 * 4)       // 171008
#define OFF_X2   (OFF_XL + 14 * 128 * 4)       // 178176
#define OFF_GSM  (OFF_X2 + 14 * 128 * 4)       // 185344
#define SZ_GSM   (14 * 608 * 4)                // 34048
#define OFF_M4   (OFF_GSM + SZ_GSM)            // 219392
#define OFF_LEN  (OFF_M4 + 256)                // 219648
#define SMEM_TOT (OFF_LEN + 64)                // 219712

typedef unsigned long long ull;

__device__ __forceinline__ void upk2(ull v, float& lo, float& hi) {
    asm("mov.b64 {%0, %1}, %2;" : "=f"(lo), "=f"(hi) : "l"(v));
}
#define FMA2(acc, a, b) asm("fma.rn.f32x2 %0, %1, %2, %3;" : "=l"(acc) : "l"(a), "l"(b), "l"(acc))

__global__ __launch_bounds__(960, 1)
void fused_kernel(float* __restrict__ out,
                  const float* __restrict__ img,
                  const float* __restrict__ lin1_w,
                  const float* __restrict__ lin1_b,
                  const float* __restrict__ w_ih,
                  const float* __restrict__ w_hh,
                  const float* __restrict__ b_ih,
                  const float* __restrict__ b_hh,
                  const float* __restrict__ lin2_w,
                  const float* __restrict__ lin2_b,
                  int hasLens) {
    extern __shared__ __align__(16) char smraw[];
    float4* wsm4 = reinterpret_cast<float4*>(smraw + OFF_W);
    float*  xh   = reinterpret_cast<float*>(smraw + OFF_XH);
    float*  xl   = reinterpret_cast<float*>(smraw + OFF_XL);
    float*  xp2  = reinterpret_cast<float*>(smraw + OFF_X2);
    float*  gsm  = reinterpret_cast<float*>(smraw + OFF_GSM);
    float*  m4   = reinterpret_cast<float*>(smraw + OFF_M4);
    int*    lensm= reinterpret_cast<int*>(smraw + OFF_LEN);

    const int tid = threadIdx.x;
    const int bid = blockIdx.x;
    int base, nv;
    if (bid < 124) { base = bid * 14; nv = 14; }
    else           { base = 1736 + (bid - 124) * 13; nv = 13; }

    const bool isSplit = (tid < 704);
    const int  row  = isSplit ? (tid >> 1) : (tid - 352);   // output row
    const int  half = tid & 1;                              // split threads only
    const int  g0   = half << 4;                            // first granule (split)

    // combined bias for this row
    float bias;
    if (row < 256)      bias = b_ih[row] + b_hh[row];
    else if (row < 384) bias = b_ih[row];
    else if (row < 512) bias = b_hh[row - 128];
    else                bias = lin2_b[row - 512];

    // ---- fill SMEM weights rows [0,NWS), layout [g][row] --------------------
    {
        const float4* wih4 = reinterpret_cast<const float4*>(w_ih);
        const float4* whh4 = reinterpret_cast<const float4*>(w_hh);
        for (int idx = tid; idx < 32 * NWS; idx += NT) {
            int g = idx / NWS;
            int r = idx - g * NWS;
            float4 a = wih4[r * 32 + g];
            if (r < 256) {
                float4 b = whh4[r * 32 + g];
                a.x += b.x; a.y += b.y; a.z += b.z; a.w += b.w;
            }
            wsm4[idx] = a;
        }
    }

    // zero x buffers, lens
    for (int m = tid; m < 14 * 128; m += NT) { xh[m] = 0.f; xl[m] = 0.f; xp2[m] = 0.f; }
    if (tid < 16) lensm[tid] = 0;

    // ---- Phase A: lin1 -> ht rows for this CTA (staged in gsm) --------------
    {
        const int j  = tid & 127;
        const int ks = tid >> 7;          // 0..3 for tid<512
        ull acc[14];
#pragma unroll
        for (int r = 0; r < 14; r++) acc[r] = 0ull;

        float4*       xs4 = reinterpret_cast<float4*>(gsm);
        const float4* im4 = reinterpret_cast<const float4*>(img);
        const ulonglong2* xs2 = reinterpret_cast<const ulonglong2*>(gsm);

        for (int kc = 0; kc < 16; kc++) {
            __syncthreads();
            for (int m = tid; m < 14 * 64; m += NT) {
                int r = m >> 6, kk4 = m & 63;
                float4 v = make_float4(0.f, 0.f, 0.f, 0.f);
                if (r < nv) v = im4[(size_t)(base + r) * 1024 + kc * 64 + kk4];
                xs4[r * 64 + kk4] = v;
            }
            __syncthreads();
            if (tid < 512) {
                const ulonglong2* wl = reinterpret_cast<const ulonglong2*>(
                    lin1_w + (size_t)j * 4096 + kc * 256 + ks * 64);
#pragma unroll 4
                for (int q = 0; q < 16; q++) {
                    ulonglong2 wv = wl[q];
#pragma unroll
                    for (int r = 0; r < 14; r++) {
                        ulonglong2 xv = xs2[r * 64 + ks * 16 + q];
                        FMA2(acc[r], wv.x, xv.x);
                        FMA2(acc[r], wv.y, xv.y);
                    }
                }
            }
        }
        __syncthreads();
        if (tid < 512) {
#pragma unroll
            for (int r = 0; r < 14; r++) {
                float lo, hi; upk2(acc[r], lo, hi);
                gsm[r * 512 + ks * 128 + j] = lo + hi;
            }
        }
        __syncthreads();
        for (int m = tid; m < 14 * 128; m += NT) {
            int r = m >> 7, jj = m & 127;
            float v = gsm[r * 512 + jj] + gsm[r * 512 + 128 + jj]
                    + gsm[r * 512 + 256 + jj] + gsm[r * 512 + 384 + jj] + lin1_b[jj];
            xh[r * 128 + jj] = (v >= 0.f) ? v : 0.01f * v;
        }
        __syncthreads();
    }

    // x source: rows < 512 read h; rows >= 512 (lin2) read leaky(h).
    // Warp-clean: threads 0..863 -> xh, 864..959 -> xl.
    const ulonglong2* xs = (row < 512) ? reinterpret_cast<const ulonglong2*>(xh)
                                       : reinterpret_cast<const ulonglong2*>(xl);
    const ulonglong2* wsm2 = reinterpret_cast<const ulonglong2*>(wsm4);

    // streamed weight pointer
    const ulonglong2* wg = nullptr;
    if (isSplit) {
        if (row >= NWS)   // rows 320..351 are w_ih rows
            wg = reinterpret_cast<const ulonglong2*>(w_ih + (size_t)row * 128 + half * 64);
    } else {
        const float* p;
        if (row < 384)      p = w_ih  + (size_t)row * 128;
        else if (row < 512) p = w_hh  + (size_t)(row - 128) * 128;
        else                p = lin2_w + (size_t)(row - 512) * 128;
        wg = reinterpret_cast<const ulonglong2*>(p);
    }

    // ---- steady-state matvec ------------------------------------------------
    auto matvec = [&]() {
        if (isSplit) {
            ull acc[14];
#pragma unroll
            for (int r = 0; r < 14; r++) acc[r] = 0ull;
            if (row < NWS) {
#pragma unroll 4
                for (int g16 = 0; g16 < 16; g16++) {
                    ulonglong2 w = wsm2[(g0 + g16) * NWS + row];
#pragma unroll
                    for (int r = 0; r < 14; r++) {
                        ulonglong2 xv = xs[r * 32 + g0 + g16];
                        FMA2(acc[r], w.x, xv.x);
                        FMA2(acc[r], w.y, xv.y);
                    }
                }
            } else {
                ulonglong2 cn0 = wg[0], cn1 = wg[1];
#pragma unroll 1
                for (int blk = 0; blk < 8; blk++) {
                    ulonglong2 c0 = cn0, c1 = cn1;
                    if (blk < 7) { cn0 = wg[blk * 2 + 2]; cn1 = wg[blk * 2 + 3]; }
#pragma unroll
                    for (int r = 0; r < 14; r++) {
                        ulonglong2 xv = xs[r * 32 + g0 + blk * 2];
                        FMA2(acc[r], c0.x, xv.x);
                        FMA2(acc[r], c0.y, xv.y);
                    }
#pragma unroll
                    for (int r = 0; r < 14; r++) {
                        ulonglong2 xv = xs[r * 32 + g0 + blk * 2 + 1];
                        FMA2(acc[r], c1.x, xv.x);
                        FMA2(acc[r], c1.y, xv.y);
                    }
                }
            }
#pragma unroll
            for (int r = 0; r < 14; r++) {
                float lo, hi; upk2(acc[r], lo, hi);
                float part = lo + hi;
                part += __shfl_xor_sync(0xffffffffu, part, 1);
                if (half == 0) gsm[r * 608 + row] = part + bias;
            }
        } else {
            ull acc[14];
#pragma unroll
            for (int r = 0; r < 14; r++) acc[r] = 0ull;
            ulonglong2 bn[4];
#pragma unroll
            for (int q = 0; q < 4; q++) bn[q] = wg[q];
#pragma unroll 1
            for (int blk = 0; blk < 8; blk++) {
                ulonglong2 b[4];
#pragma unroll
                for (int q = 0; q < 4; q++) b[q] = bn[q];
                if (blk < 7) {
#pragma unroll
                    for (int q = 0; q < 4; q++) bn[q] = wg[blk * 4 + 4 + q];
                }
#pragma unroll
                for (int q = 0; q < 4; q++) {
#pragma unroll
                    for (int r = 0; r < 14; r++) {
                        ulonglong2 xv = xs[r * 32 + blk * 4 + q];
                        FMA2(acc[r], b[q].x, xv.x);
                        FMA2(acc[r], b[q].y, xv.y);
                    }
                }
            }
#pragma unroll
            for (int r = 0; r < 14; r++) {
                float lo, hi; upk2(acc[r], lo, hi);
                gsm[r * 608 + row] = lo + hi + bias;
            }
        }
    };

    // ---- step-1 matvec: x = ht, h = 0; gate rows (<384) use raw w_ih --------
    auto matvec1 = [&]() {
        const ulonglong2* xg = reinterpret_cast<const ulonglong2*>(xh);
        if (isSplit) {
            // all split rows < 352 < 384: active
            const ulonglong2* w1 = reinterpret_cast<const ulonglong2*>(
                w_ih + (size_t)row * 128 + half * 64);
            ull acc[14];
#pragma unroll
            for (int r = 0; r < 14; r++) acc[r] = 0ull;
#pragma unroll 2
            for (int g16 = 0; g16 < 16; g16++) {
                ulonglong2 w = w1[g16];
#pragma unroll
                for (int r = 0; r < 14; r++) {
                    ulonglong2 xv = xg[r * 32 + g0 + g16];
                    FMA2(acc[r], w.x, xv.x);
                    FMA2(acc[r], w.y, xv.y);
                }
            }
#pragma unroll
            for (int r = 0; r < 14; r++) {
                float lo, hi; upk2(acc[r], lo, hi);
                float part = lo + hi;
                part += __shfl_xor_sync(0xffffffffu, part, 1);
                if (half == 0) gsm[r * 608 + row] = part + bias;
            }
        } else {
            ull acc[14];
#pragma unroll
            for (int r = 0; r < 14; r++) acc[r] = 0ull;
            if (row < 384) {
                const ulonglong2* w1 = reinterpret_cast<const ulonglong2*>(
                    w_ih + (size_t)row * 128);
#pragma unroll 2
                for (int g = 0; g < 32; g++) {
                    ulonglong2 w = w1[g];
#pragma unroll
                    for (int r = 0; r < 14; r++) {
                        ulonglong2 xv = xg[r * 32 + g];
                        FMA2(acc[r], w.x, xv.x);
                        FMA2(acc[r], w.y, xv.y);
                    }
                }
            }
#pragma unroll
            for (int r = 0; r < 14; r++) {
                float lo, hi; upk2(acc[r], lo, hi);
                gsm[r * 608 + row] = lo + hi + bias;
            }
        }
    };

    // ---- GRU gates + state rotation + per-row char maxima -------------------
    auto gatephase = [&](bool step1) -> bool {
        bool changed = false;
        for (int m = tid; m < 14 * HH; m += NT) {
            int r = m >> 7, k = m & 127;
            if (r < nv) {
                float rpre = gsm[r * 608 + k];
                float zpre = gsm[r * 608 + 128 + k];
                float inp  = gsm[r * 608 + 256 + k];
                float hnp  = gsm[r * 608 + 384 + k];
                float rg = __fdividef(1.0f, 1.0f + __expf(-rpre));
                float zg = __fdividef(1.0f, 1.0f + __expf(-zpre));
                float n  = tanhf(inp + rg * hnp);
                int   xi = r * 128 + k;
                float xold = xh[xi];
                float old2 = xp2[xi];
                float hn = step1 ? (1.0f - zg) * n
                                 : (1.0f - zg) * n + zg * xold;
                changed |= (__float_as_int(hn) != __float_as_int(old2));
                xp2[xi] = xold;
                xh[xi]  = hn;
                xl[xi]  = (hn >= 0.f) ? hn : 0.01f * hn;
            }
        }
        if (tid < 56) {
            int r = tid >> 2, q = tid & 3;
            float mx = -3.4e38f;
#pragma unroll
            for (int c = 0; c < 24; c++) mx = fmaxf(mx, gsm[r * 608 + 512 + q * 24 + c]);
            m4[tid] = mx;
        }
        return changed;
    };

    const float THR = (float)(1.0 - 1e-05);

    // pre-step: hn0 = GRU(ht, 0)
    matvec1();
    __syncthreads();
    gatephase(true);
    __syncthreads();

    float cval[2], pval[2];
    int   foff[2];
    int   nslots = 0;
    int   sConv = -1;

    for (int s = 0; s < TSTEPS; s++) {
        matvec();
        __syncthreads();
        bool changed = gatephase(false);
        if (s == 0) changed = true;               // xp2 invalid at s=0
        int cnt = __syncthreads_count(changed ? 1 : 0);

#pragma unroll
        for (int q = 0; q < 2; q++) pval[q] = cval[q];
        nslots = 0;
        for (int m = tid; m < nv * CC; m += NT) {
            int r = m / CC, c = m - r * CC;
            float mx = fmaxf(fmaxf(m4[r * 4 + 0], m4[r * 4 + 1]),
                             fmaxf(m4[r * 4 + 2], m4[r * 4 + 3]));
            float ch = gsm[r * 608 + 512 + c];
            float cn = __fdiv_rn(ch, mx);
            float val = (cn > THR) ? cn : 0.f;
            int off = (base + r) * (TSTEPS * CC) + c;
            out[(size_t)off + (size_t)s * CC] = val;
            if (c == 52 && val == 1.0f && lensm[r] == 0) lensm[r] = s + 1;
            cval[nslots] = val;
            foff[nslots] = off;
            nslots++;
        }

        if (cnt == 0) { sConv = s; break; }
        __syncthreads();
    }

    if (sConv >= 0) {
        // period-2 limit cycle: outputs alternate between steps sConv-1, sConv
        for (int s2 = sConv + 1; s2 < TSTEPS; s2++) {
            bool even = (((s2 - sConv) & 1) == 0);
#pragma unroll
            for (int q = 0; q < 2; q++) {
                if (q < nslots)
                    out[(size_t)foff[q] + (size_t)s2 * CC] = even ? cval[q] : pval[q];
            }
        }
    }

    __syncthreads();
    if (hasLens && tid < nv) {
        int L = lensm[tid];
        out[(size_t)TITLES_ELEMS + base + tid] = (float)(L == 0 ? TSTEPS : L);
    }
}

// ------------------------------- launch -------------------------------------
extern "C" void kernel_launch(void* const* d_in, const int* in_sizes, int n_in,
                              void* d_out, int out_size) {
    const float* img_feat = (const float*)d_in[0];
    const float* lin1_w   = (const float*)d_in[1];
    const float* lin1_b   = (const float*)d_in[2];
    const float* w_ih     = (const float*)d_in[3];
    const float* w_hh     = (const float*)d_in[4];
    const float* b_ih     = (const float*)d_in[5];
    const float* b_hh     = (const float*)d_in[6];
    const float* lin2_w   = (const float*)d_in[7];
    const float* lin2_b   = (const float*)d_in[8];

    cudaFuncSetAttribute(fused_kernel,
                         cudaFuncAttributeMaxDynamicSharedMemorySize, SMEM_TOT);

    int hasLens = (out_size >= TITLES_ELEMS + BB) ? 1 : 0;
    fused_kernel<<<148, 960, SMEM_TOT>>>((float*)d_out, img_feat, lin1_w, lin1_b,
                                         w_ih, w_hh, b_ih, b_hh, lin2_w, lin2_b,
                                         hasLens);
}